// round 15
// baseline (speedup 1.0000x reference)
#include <cuda_runtime.h>
#include <math.h>

// Gaussian-mixture splat renderer, forward-differenced along grid columns.
// R12 math (packed k-pair chains + packed epilogue, SMEM-staged coalesced
// stores) at PIX=24: 295k threads -> 97% theoretical occupancy with 1.3-wave
// backfill, while keeping seed amortization close to PIX=32 and regs at 40.
//
// c = x_idx*H + y_idx ; px = x_idx/(W-1), py = y_idx/(H-1).
// Per Gaussian k (prescaled by SC = sqrt(0.5*log2 e)):
//   t0 = s10*py + (s00*px + C0),  t1 = s11*py + A1,  e_k = exp2(-(t0^2+t1^2))
// FD along a column: e <- e*r, r <- r*rr, rr = exp2(-2 h^2 (s10^2+s11^2))
// out = saturate( sum_k w_k e_k / max(1e-7, sum_k e_k) )

#define NK 4
#define PIX 24
#define NGRP (PIX / 4)     // 6 groups of 4 pixels
#define THR 128            // 4 warps
#define WARPS 4
#define GM_EPS 1e-7f

typedef unsigned long long u64t;

__device__ __forceinline__ float ex2(float x) {
    float y; asm("ex2.approx.ftz.f32 %0, %1;" : "=f"(y) : "f"(x)); return y;
}
__device__ __forceinline__ u64t pk2(float lo, float hi) {
    u64t r; asm("mov.b64 %0, {%1, %2};" : "=l"(r) : "f"(lo), "f"(hi)); return r;
}
__device__ __forceinline__ void upk2(u64t v, float& lo, float& hi) {
    asm("mov.b64 {%0, %1}, %2;" : "=f"(lo), "=f"(hi) : "l"(v));
}
__device__ __forceinline__ u64t mul2(u64t a, u64t b) {
    u64t d; asm("mul.rn.f32x2 %0, %1, %2;" : "=l"(d) : "l"(a), "l"(b)); return d;
}
__device__ __forceinline__ u64t add2(u64t a, u64t b) {
    u64t d; asm("add.rn.f32x2 %0, %1, %2;" : "=l"(d) : "l"(a), "l"(b)); return d;
}
__device__ __forceinline__ u64t fma2(u64t a, u64t b, u64t c) {
    u64t d; asm("fma.rn.f32x2 %0, %1, %2, %3;" : "=l"(d) : "l"(a), "l"(b), "l"(c)); return d;
}

// ---------------------------------------------------------------------------
// Main kernel. Lane l of global-warp gw owns pixels [gw*768 + 24l, +24).
// Requires H % 24 == 0 and HW % 3072 == 0.
//
// SMEM tile (per warp, 224 float4 = 3584 B, 7 slots per lane: 6 used + 1 pad):
//   write:  tw[7*l + g], g = 0..5.  Slot mod 8 = (g - l) mod 8 per 8-lane
//           phase -> 8 distinct values -> conflict-free STS.128.
//   read :  output float4 f = 32*i + l (i = 0..5): producer lane lp = f/6,
//           group g = f - 6*lp -> tw[f + lp]. (<=2-way on rare phases.)
// ---------------------------------------------------------------------------
__global__ void __launch_bounds__(THR, 12) gmix_fd(
    const float* __restrict__ params,
    float* __restrict__ out,
    int H, int HW, float inv_wm1, float inv_hm1)
{
    __shared__ float4 tile[WARPS][224];   // 14336 B total

    const int warp = threadIdx.x >> 5;
    const int lane = threadIdx.x & 31;
    const int gw   = blockIdx.x * WARPS + warp;
    const int n    = blockIdx.y;
    const int c0   = gw * (32 * PIX) + lane * PIX;
    if (c0 >= HW) return;

    const float4* p4 = reinterpret_cast<const float4*>(params + n * 28);
    const float4 MUX = __ldg(p4 + 0);
    const float4 MUY = __ldg(p4 + 1);
    const float4 WKV = __ldg(p4 + 2);
    const float4 SG0 = __ldg(p4 + 3);   // {s00, s01(ignored), s10, s11}
    const float4 SG1 = __ldg(p4 + 4);
    const float4 SG2 = __ldg(p4 + 5);
    const float4 SG3 = __ldg(p4 + 6);

    const float mux[NK] = {MUX.x, MUX.y, MUX.z, MUX.w};
    const float muy[NK] = {MUY.x, MUY.y, MUY.z, MUY.w};
    const float SC = 0.84932180f;       // sqrt(0.5 * log2 e)
    const float s00[NK] = {SG0.x * SC, SG1.x * SC, SG2.x * SC, SG3.x * SC};
    const float s10[NK] = {SG0.z * SC, SG1.z * SC, SG2.z * SC, SG3.z * SC};
    const float s11[NK] = {SG0.w * SC, SG1.w * SC, SG2.w * SC, SG3.w * SC};

    const int   x_idx = c0 / H;
    const int   y0    = c0 - x_idx * H;
    const float px    = (float)x_idx * inv_wm1;
    const float py0   = (float)y0 * inv_hm1;
    const float h     = inv_hm1;

    // Derive FD constants, seed e and r at the first pixel of this run.
    float es[NK], rs[NK], rrs[NK];
#pragma unroll
    for (int k = 0; k < NK; k++) {
        const float C0  = -(s00[k] * mux[k] + s10[k] * muy[k]);
        const float A1  = -s11[k] * muy[k];
        const float a   = fmaf(s10[k], s10[k], s11[k] * s11[k]);
        const float w0n = -(h * h) * a;
        const float un  = -2.0f * h * s10[k];
        const float vn  = -2.0f * h * s11[k];
        rrs[k] = ex2(w0n + w0n);

        const float a0 = fmaf(s00[k], px, C0);
        const float t0 = fmaf(s10[k], py0, a0);
        const float t1 = fmaf(s11[k], py0, A1);
        es[k] = ex2(fmaf(-t0, t0, -t1 * t1));
        rs[k] = ex2(fmaf(un, t0, fmaf(vn, t1, w0n)));
    }

    // Packed chain state over k-pairs.
    u64t E01 = pk2(es[0], es[1]), E23 = pk2(es[2], es[3]);
    u64t R01 = pk2(rs[0], rs[1]), R23 = pk2(rs[2], rs[3]);
    const u64t RR01 = pk2(rrs[0], rrs[1]), RR23 = pk2(rrs[2], rrs[3]);
    const u64t W01  = pk2(WKV.x, WKV.y),   W23  = pk2(WKV.z, WKV.w);

    float4* tw = tile[warp];
    const int wbase = 7 * lane;

#pragma unroll
    for (int grp = 0; grp < NGRP; grp++) {
        float4 res;
        float* rp = &res.x;
#pragma unroll
        for (int q = 0; q < 4; q++) {
            if (!(grp == 0 && q == 0)) {
                E01 = mul2(E01, R01);
                E23 = mul2(E23, R23);
                R01 = mul2(R01, RR01);
                R23 = mul2(R23, RR23);
            }
            const u64t G2 = add2(E01, E23);
            const u64t A2 = fma2(W01, E01, mul2(W23, E23));
            float g0, g1, a0, a1;
            upk2(G2, g0, g1);
            upk2(A2, a0, a1);
            rp[q] = __saturatef(
                __fdividef(a0 + a1, fmaxf(GM_EPS, g0 + g1)));
        }
        tw[wbase + grp] = res;                     // STS.128, conflict-free
    }

    __syncwarp();

    // Coalesced drain: warp writes 6 x 512B contiguous chunks.
    float4* ob = reinterpret_cast<float4*>(out + (size_t)n * (size_t)HW
                                               + (size_t)gw * (32 * PIX));
#pragma unroll
    for (int i = 0; i < NGRP; i++) {
        const int f  = 32 * i + lane;
        const int lp = f / 6;                      // compile-time-strength div
        ob[f] = tw[f + lp];                        // tw[7*lp + (f - 6*lp)]
    }
}

// ---------------------------------------------------------------------------
// Fallback: per-pixel direct evaluation (odd shapes).
// ---------------------------------------------------------------------------
__global__ void __launch_bounds__(256) gmix_generic(
    const float* __restrict__ params,
    float* __restrict__ out,
    int H, int HW, float inv_wm1, float inv_hm1)
{
    const int n = blockIdx.y;
    const float* p = params + n * 28;
    float mux[NK], muy[NK], wkk[NK], s00[NK], s10[NK], s11[NK];
#pragma unroll
    for (int k = 0; k < NK; k++) {
        mux[k] = __ldg(p + k);        muy[k] = __ldg(p + 4 + k);
        wkk[k] = __ldg(p + 8 + k);
        s00[k] = __ldg(p + 12 + 4*k + 0);
        s10[k] = __ldg(p + 12 + 4*k + 2);
        s11[k] = __ldg(p + 12 + 4*k + 3);
    }
    const int c = blockIdx.x * blockDim.x + threadIdx.x;
    if (c >= HW) return;
    const int x_idx = c / H, y_idx = c - x_idx * H;
    const float px = (float)x_idx * inv_wm1, py = (float)y_idx * inv_hm1;
    float g = 0.0f, acc = 0.0f;
#pragma unroll
    for (int k = 0; k < NK; k++) {
        const float d0 = px - mux[k], d1 = py - muy[k];
        const float t0 = fmaf(s00[k], d0, s10[k] * d1);
        const float t1 = s11[k] * d1;
        const float e  = __expf(-0.5f * fmaf(t0, t0, t1 * t1));
        g += e;
        acc = fmaf(wkk[k], e, acc);
    }
    out[(size_t)n * (size_t)HW + c] =
        __saturatef(__fdividef(acc, fmaxf(GM_EPS, g)));
}

// ---------------------------------------------------------------------------
extern "C" void kernel_launch(void* const* d_in, const int* in_sizes, int n_in,
                              void* d_out, int out_size)
{
    int pi = 0;
    for (int i = 1; i < n_in; i++)
        if (in_sizes[i] > in_sizes[pi]) pi = i;
    const float* params = (const float*)d_in[pi];

    const int N  = in_sizes[pi] / 28;
    const int HW = out_size / N;
    int H = (int)(sqrt((double)HW) + 0.5);
    while (H > 1 && (HW % H) != 0) H--;
    const int W = HW / H;

    const float inv_wm1 = 1.0f / (float)(W - 1);
    const float inv_hm1 = 1.0f / (float)(H - 1);

    const int px_per_block = THR * PIX;   // 3072
    if ((H % PIX) == 0 && (HW % px_per_block) == 0) {
        dim3 grid(HW / px_per_block, N);
        gmix_fd<<<grid, THR>>>(params, (float*)d_out,
                               H, HW, inv_wm1, inv_hm1);
    } else {
        const int threads = 256;
        dim3 grid((HW + threads - 1) / threads, N);
        gmix_generic<<<grid, threads>>>(params, (float*)d_out,
                                        H, HW, inv_wm1, inv_hm1);
    }
}

// round 16
// speedup vs baseline: 1.0521x; 1.0521x over previous
#include <cuda_runtime.h>
#include <math.h>

// Gaussian-mixture splat renderer, forward-differenced along grid columns.
// R12 shell (PIX=32, 128thr, XOR-swizzled SMEM-staged coalesced stores) with
// PIXEL-PAIR lane packing: f32x2 lanes hold (pixel j, pixel j+1), so the
// mixture sums for two pixels emerge in single packed registers and the
// scalar epilogue halves.
//
// c = x_idx*H + y_idx ; px = x_idx/(W-1), py = y_idx/(H-1).
// Per Gaussian k (prescaled by SC = sqrt(0.5*log2 e)):
//   t0 = s10*py + (s00*px + C0),  t1 = s11*py + A1,  e_k = exp2(-(t0^2+t1^2))
// Single-step FD: e_{j+1} = e_j r_j, r_{j+1} = r_j rr, rr = exp2(-2h^2 a)
// Pair-step (lanes = pixels j, j+1):
//   E_k = (e_j, e_{j+1}),  Q_k = (r_j^2 rr, r_{j+1}^2 rr)
//   E_k <- E_k * Q_k ;  Q_k <- Q_k * rr^4
// out = saturate( sum_k w_k e_k / max(1e-7, sum_k e_k) )

#define NK 4
#define PIX 32
#define THR 128          // 4 warps
#define WARPS 4
#define GM_EPS 1e-7f

typedef unsigned long long u64t;

__device__ __forceinline__ float ex2(float x) {
    float y; asm("ex2.approx.ftz.f32 %0, %1;" : "=f"(y) : "f"(x)); return y;
}
__device__ __forceinline__ u64t pk2(float lo, float hi) {
    u64t r; asm("mov.b64 %0, {%1, %2};" : "=l"(r) : "f"(lo), "f"(hi)); return r;
}
__device__ __forceinline__ void upk2(u64t v, float& lo, float& hi) {
    asm("mov.b64 {%0, %1}, %2;" : "=f"(lo), "=f"(hi) : "l"(v));
}
__device__ __forceinline__ u64t mul2(u64t a, u64t b) {
    u64t d; asm("mul.rn.f32x2 %0, %1, %2;" : "=l"(d) : "l"(a), "l"(b)); return d;
}
__device__ __forceinline__ u64t add2(u64t a, u64t b) {
    u64t d; asm("add.rn.f32x2 %0, %1, %2;" : "=l"(d) : "l"(a), "l"(b)); return d;
}
__device__ __forceinline__ u64t fma2(u64t a, u64t b, u64t c) {
    u64t d; asm("fma.rn.f32x2 %0, %1, %2, %3;" : "=l"(d) : "l"(a), "l"(b), "l"(c)); return d;
}

// ---------------------------------------------------------------------------
// Main kernel. Lane l of global-warp gw owns pixels [gw*1024 + 32l, +32).
// Requires H % 32 == 0 and HW % 4096 == 0.
//
// SMEM tile (per warp, 256 float4 = 4096 B, XOR-swizzled, no padding):
//   write:  tw[8*l + (g ^ (l & 7))]           g = group 0..7
//   read :  output float4 f = 32*i + l: producer lane lp = 4i+(l>>3),
//           slot g = l&7  ->  tw[8*lp + ((l&7) ^ (lp & 7))]
// ---------------------------------------------------------------------------
__global__ void __launch_bounds__(THR, 12) gmix_fd(
    const float* __restrict__ params,
    float* __restrict__ out,
    int H, int HW, float inv_wm1, float inv_hm1)
{
    __shared__ float4 tile[WARPS][256];   // 16384 B total

    const int warp = threadIdx.x >> 5;
    const int lane = threadIdx.x & 31;
    const int gw   = blockIdx.x * WARPS + warp;
    const int n    = blockIdx.y;
    const int c0   = gw * (32 * PIX) + lane * PIX;
    if (c0 >= HW) return;

    const float4* p4 = reinterpret_cast<const float4*>(params + n * 28);
    const float4 MUX = __ldg(p4 + 0);
    const float4 MUY = __ldg(p4 + 1);
    const float4 WKV = __ldg(p4 + 2);
    const float4 SG0 = __ldg(p4 + 3);   // {s00, s01(ignored), s10, s11}
    const float4 SG1 = __ldg(p4 + 4);
    const float4 SG2 = __ldg(p4 + 5);
    const float4 SG3 = __ldg(p4 + 6);

    const float mux[NK] = {MUX.x, MUX.y, MUX.z, MUX.w};
    const float muy[NK] = {MUY.x, MUY.y, MUY.z, MUY.w};
    const float wv [NK] = {WKV.x, WKV.y, WKV.z, WKV.w};
    const float SC = 0.84932180f;       // sqrt(0.5 * log2 e)
    const float s00[NK] = {SG0.x * SC, SG1.x * SC, SG2.x * SC, SG3.x * SC};
    const float s10[NK] = {SG0.z * SC, SG1.z * SC, SG2.z * SC, SG3.z * SC};
    const float s11[NK] = {SG0.w * SC, SG1.w * SC, SG2.w * SC, SG3.w * SC};

    const int   x_idx = c0 / H;
    const int   y0    = c0 - x_idx * H;
    const float px    = (float)x_idx * inv_wm1;
    const float py0   = (float)y0 * inv_hm1;
    const float h     = inv_hm1;

    // Seed packed pixel-pair state per Gaussian.
    u64t E[NK], Q[NK], RR4[NK], W[NK];
#pragma unroll
    for (int k = 0; k < NK; k++) {
        const float C0  = -(s00[k] * mux[k] + s10[k] * muy[k]);
        const float A1  = -s11[k] * muy[k];
        const float a   = fmaf(s10[k], s10[k], s11[k] * s11[k]);
        const float w0n = -(h * h) * a;
        const float un  = -2.0f * h * s10[k];
        const float vn  = -2.0f * h * s11[k];

        const float a0 = fmaf(s00[k], px, C0);
        const float t0 = fmaf(s10[k], py0, a0);
        const float t1 = fmaf(s11[k], py0, A1);

        const float e0 = ex2(fmaf(-t0, t0, -t1 * t1));
        const float r0 = ex2(fmaf(un, t0, fmaf(vn, t1, w0n)));
        const float rr = ex2(w0n + w0n);

        const float e1  = e0 * r0;
        const float rr2 = rr * rr;
        const float rr4 = rr2 * rr2;
        const float q0  = r0 * r0 * rr;      // 2-step ratio, even lane
        const float q1  = q0 * rr2;          // 2-step ratio, odd lane

        E[k]   = pk2(e0, e1);
        Q[k]   = pk2(q0, q1);
        RR4[k] = pk2(rr4, rr4);
        W[k]   = pk2(wv[k], wv[k]);
    }

    float4* tw = tile[warp];
    const int wslot = 8 * lane;

#pragma unroll
    for (int grp = 0; grp < PIX / 4; grp++) {
        float4 res;
        float* rp = &res.x;
#pragma unroll
        for (int pq = 0; pq < 2; pq++) {         // one iter = 2 pixels
            if (!(grp == 0 && pq == 0)) {
                E[0] = mul2(E[0], Q[0]);  E[1] = mul2(E[1], Q[1]);
                E[2] = mul2(E[2], Q[2]);  E[3] = mul2(E[3], Q[3]);
                Q[0] = mul2(Q[0], RR4[0]); Q[1] = mul2(Q[1], RR4[1]);
                Q[2] = mul2(Q[2], RR4[2]); Q[3] = mul2(Q[3], RR4[3]);
            }
            // Packed epilogue: both pixels' sums in single registers.
            const u64t G = add2(add2(E[0], E[1]), add2(E[2], E[3]));
            const u64t A = fma2(W[0], E[0],
                           fma2(W[1], E[1],
                           fma2(W[2], E[2], mul2(W[3], E[3]))));
            float g0, g1, a0, a1;
            upk2(G, g0, g1);
            upk2(A, a0, a1);
            rp[2 * pq]     = __saturatef(__fdividef(a0, fmaxf(GM_EPS, g0)));
            rp[2 * pq + 1] = __saturatef(__fdividef(a1, fmaxf(GM_EPS, g1)));
        }
        tw[wslot + (grp ^ (lane & 7))] = res;    // STS.128, conflict-free
    }

    __syncwarp();

    // Coalesced drain: warp writes 8 x 512B contiguous chunks.
    float4* ob = reinterpret_cast<float4*>(out + (size_t)n * (size_t)HW
                                               + (size_t)gw * (32 * PIX));
#pragma unroll
    for (int i = 0; i < 8; i++) {
        const int lp = 4 * i + (lane >> 3);
        ob[32 * i + lane] = tw[8 * lp + ((lane & 7) ^ (lp & 7))];
    }
}

// ---------------------------------------------------------------------------
// Fallback: per-pixel direct evaluation (odd shapes).
// ---------------------------------------------------------------------------
__global__ void __launch_bounds__(256) gmix_generic(
    const float* __restrict__ params,
    float* __restrict__ out,
    int H, int HW, float inv_wm1, float inv_hm1)
{
    const int n = blockIdx.y;
    const float* p = params + n * 28;
    float mux[NK], muy[NK], wkk[NK], s00[NK], s10[NK], s11[NK];
#pragma unroll
    for (int k = 0; k < NK; k++) {
        mux[k] = __ldg(p + k);        muy[k] = __ldg(p + 4 + k);
        wkk[k] = __ldg(p + 8 + k);
        s00[k] = __ldg(p + 12 + 4*k + 0);
        s10[k] = __ldg(p + 12 + 4*k + 2);
        s11[k] = __ldg(p + 12 + 4*k + 3);
    }
    const int c = blockIdx.x * blockDim.x + threadIdx.x;
    if (c >= HW) return;
    const int x_idx = c / H, y_idx = c - x_idx * H;
    const float px = (float)x_idx * inv_wm1, py = (float)y_idx * inv_hm1;
    float g = 0.0f, acc = 0.0f;
#pragma unroll
    for (int k = 0; k < NK; k++) {
        const float d0 = px - mux[k], d1 = py - muy[k];
        const float t0 = fmaf(s00[k], d0, s10[k] * d1);
        const float t1 = s11[k] * d1;
        const float e  = __expf(-0.5f * fmaf(t0, t0, t1 * t1));
        g += e;
        acc = fmaf(wkk[k], e, acc);
    }
    out[(size_t)n * (size_t)HW + c] =
        __saturatef(__fdividef(acc, fmaxf(GM_EPS, g)));
}

// ---------------------------------------------------------------------------
extern "C" void kernel_launch(void* const* d_in, const int* in_sizes, int n_in,
                              void* d_out, int out_size)
{
    int pi = 0;
    for (int i = 1; i < n_in; i++)
        if (in_sizes[i] > in_sizes[pi]) pi = i;
    const float* params = (const float*)d_in[pi];

    const int N  = in_sizes[pi] / 28;
    const int HW = out_size / N;
    int H = (int)(sqrt((double)HW) + 0.5);
    while (H > 1 && (HW % H) != 0) H--;
    const int W = HW / H;

    const float inv_wm1 = 1.0f / (float)(W - 1);
    const float inv_hm1 = 1.0f / (float)(H - 1);

    const int px_per_block = THR * PIX;   // 4096
    if ((H % PIX) == 0 && (HW % px_per_block) == 0) {
        dim3 grid(HW / px_per_block, N);
        gmix_fd<<<grid, THR>>>(params, (float*)d_out,
                               H, HW, inv_wm1, inv_hm1);
    } else {
        const int threads = 256;
        dim3 grid((HW + threads - 1) / threads, N);
        gmix_generic<<<grid, threads>>>(params, (float*)d_out,
                                        H, HW, inv_wm1, inv_hm1);
    }
}

// round 17
// speedup vs baseline: 1.1317x; 1.0756x over previous
#include <cuda_runtime.h>
#include <math.h>

// Gaussian-mixture splat renderer, forward-differenced along grid columns.
// Final consolidation of the R16 design: PIX=32 column ownership, packed
// pixel-pair f32x2 chains, packed epilogue, XOR-swizzled SMEM staging with
// fully coalesced 512B warp stores. This round trims non-loop overhead:
// exact-grid (no bounds guard), strength-reduced drain indexing, and a
// predicate-free chain advance.
//
// c = x_idx*H + y_idx ; px = x_idx/(W-1), py = y_idx/(H-1).
// Per Gaussian k (prescaled by SC = sqrt(0.5*log2 e)):
//   t0 = s10*py + (s00*px + C0),  t1 = s11*py + A1,  e_k = exp2(-(t0^2+t1^2))
// Single-step FD: e_{j+1} = e_j r_j, r_{j+1} = r_j rr, rr = exp2(-2h^2 a)
// Pair-step (lanes = pixels j, j+1):
//   E_k = (e_j, e_{j+1}),  Q_k = (r_j^2 rr, r_{j+1}^2 rr)
//   E_k <- E_k * Q_k ;  Q_k <- Q_k * rr^4
// out = saturate( sum_k w_k e_k / max(1e-7, sum_k e_k) )

#define NK 4
#define PIX 32
#define THR 128          // 4 warps
#define WARPS 4
#define GM_EPS 1e-7f

typedef unsigned long long u64t;

__device__ __forceinline__ float ex2(float x) {
    float y; asm("ex2.approx.ftz.f32 %0, %1;" : "=f"(y) : "f"(x)); return y;
}
__device__ __forceinline__ u64t pk2(float lo, float hi) {
    u64t r; asm("mov.b64 %0, {%1, %2};" : "=l"(r) : "f"(lo), "f"(hi)); return r;
}
__device__ __forceinline__ void upk2(u64t v, float& lo, float& hi) {
    asm("mov.b64 {%0, %1}, %2;" : "=f"(lo), "=f"(hi) : "l"(v));
}
__device__ __forceinline__ u64t mul2(u64t a, u64t b) {
    u64t d; asm("mul.rn.f32x2 %0, %1, %2;" : "=l"(d) : "l"(a), "l"(b)); return d;
}
__device__ __forceinline__ u64t add2(u64t a, u64t b) {
    u64t d; asm("add.rn.f32x2 %0, %1, %2;" : "=l"(d) : "l"(a), "l"(b)); return d;
}
__device__ __forceinline__ u64t fma2(u64t a, u64t b, u64t c) {
    u64t d; asm("fma.rn.f32x2 %0, %1, %2, %3;" : "=l"(d) : "l"(a), "l"(b), "l"(c)); return d;
}

// ---------------------------------------------------------------------------
// Main kernel. Lane l of global-warp gw owns pixels [gw*1024 + 32l, +32).
// Grid is exact (HW % 4096 == 0, H % 32 == 0 checked host-side).
//
// SMEM tile (per warp, 256 float4 = 4096 B, XOR-swizzled, no padding):
//   write:  tw[8*l + (g ^ (l & 7))]           g = group 0..7
//   read :  output float4 f = 32*i + l: producer lane lp = 4i+(l>>3),
//           slot g = l&7  ->  tw[8*lp + ((l&7) ^ (lp & 7))]
// ---------------------------------------------------------------------------
__global__ void __launch_bounds__(THR, 12) gmix_fd(
    const float* __restrict__ params,
    float* __restrict__ out,
    int H, int HW, float inv_wm1, float inv_hm1)
{
    __shared__ float4 tile[WARPS][256];   // 16384 B total

    const int warp = threadIdx.x >> 5;
    const int lane = threadIdx.x & 31;
    const int gw   = blockIdx.x * WARPS + warp;
    const int n    = blockIdx.y;
    const int c0   = gw * (32 * PIX) + lane * PIX;

    const float4* p4 = reinterpret_cast<const float4*>(params + n * 28);
    const float4 MUX = __ldg(p4 + 0);
    const float4 MUY = __ldg(p4 + 1);
    const float4 WKV = __ldg(p4 + 2);
    const float4 SG0 = __ldg(p4 + 3);   // {s00, s01(ignored), s10, s11}
    const float4 SG1 = __ldg(p4 + 4);
    const float4 SG2 = __ldg(p4 + 5);
    const float4 SG3 = __ldg(p4 + 6);

    const float mux[NK] = {MUX.x, MUX.y, MUX.z, MUX.w};
    const float muy[NK] = {MUY.x, MUY.y, MUY.z, MUY.w};
    const float wv [NK] = {WKV.x, WKV.y, WKV.z, WKV.w};
    const float SC = 0.84932180f;       // sqrt(0.5 * log2 e)
    const float s00[NK] = {SG0.x * SC, SG1.x * SC, SG2.x * SC, SG3.x * SC};
    const float s10[NK] = {SG0.z * SC, SG1.z * SC, SG2.z * SC, SG3.z * SC};
    const float s11[NK] = {SG0.w * SC, SG1.w * SC, SG2.w * SC, SG3.w * SC};

    const int   x_idx = c0 / H;
    const int   y0    = c0 - x_idx * H;
    const float px    = (float)x_idx * inv_wm1;
    const float py0   = (float)y0 * inv_hm1;
    const float h     = inv_hm1;

    // Seed packed pixel-pair state per Gaussian.
    u64t E[NK], Q[NK], RR4[NK], W[NK];
#pragma unroll
    for (int k = 0; k < NK; k++) {
        const float C0  = -(s00[k] * mux[k] + s10[k] * muy[k]);
        const float A1  = -s11[k] * muy[k];
        const float a   = fmaf(s10[k], s10[k], s11[k] * s11[k]);
        const float w0n = -(h * h) * a;
        const float un  = -2.0f * h * s10[k];
        const float vn  = -2.0f * h * s11[k];

        const float a0 = fmaf(s00[k], px, C0);
        const float t0 = fmaf(s10[k], py0, a0);
        const float t1 = fmaf(s11[k], py0, A1);

        const float e0 = ex2(fmaf(-t0, t0, -t1 * t1));
        const float r0 = ex2(fmaf(un, t0, fmaf(vn, t1, w0n)));
        const float rr = ex2(w0n + w0n);

        const float e1  = e0 * r0;
        const float rr2 = rr * rr;
        const float q0  = r0 * r0 * rr;      // 2-step ratio, even lane
        const float q1  = q0 * rr2;          // 2-step ratio, odd lane

        E[k]   = pk2(e0, e1);
        Q[k]   = pk2(q0, q1);
        RR4[k] = pk2(rr2 * rr2, rr2 * rr2);
        W[k]   = pk2(wv[k], wv[k]);
    }

    float4* tw = tile[warp];
    // This lane's 8 swizzled write slots: base + (grp ^ xorv).
    float4* const wp   = tw + 8 * lane;
    const int    wxor  = lane & 7;

#pragma unroll
    for (int grp = 0; grp < PIX / 4; grp++) {
        float4 res;
        float* rp = &res.x;
#pragma unroll
        for (int pq = 0; pq < 2; pq++) {         // one iter = 2 pixels
            // Packed epilogue: both pixels' sums in single registers.
            const u64t G = add2(add2(E[0], E[1]), add2(E[2], E[3]));
            const u64t A = fma2(W[0], E[0],
                           fma2(W[1], E[1],
                           fma2(W[2], E[2], mul2(W[3], E[3]))));
            float g0, g1, a0, a1;
            upk2(G, g0, g1);
            upk2(A, a0, a1);
            rp[2 * pq]     = __saturatef(__fdividef(a0, fmaxf(GM_EPS, g0)));
            rp[2 * pq + 1] = __saturatef(__fdividef(a1, fmaxf(GM_EPS, g1)));

            // Advance chains 2 pixels (elided after the final pair).
            if (!(grp == PIX / 4 - 1 && pq == 1)) {
                E[0] = mul2(E[0], Q[0]);  E[1] = mul2(E[1], Q[1]);
                E[2] = mul2(E[2], Q[2]);  E[3] = mul2(E[3], Q[3]);
                Q[0] = mul2(Q[0], RR4[0]); Q[1] = mul2(Q[1], RR4[1]);
                Q[2] = mul2(Q[2], RR4[2]); Q[3] = mul2(Q[3], RR4[3]);
            }
        }
        wp[grp ^ wxor] = res;                    // STS.128, conflict-free
    }

    __syncwarp();

    // Coalesced drain: warp writes 8 x 512B contiguous chunks.
    // Read slot for output float4 f=32i+l: lp = 4i+(l>>3), tw[8lp + ((l&7)^(lp&7))].
    // For fixed lane, lp&7 alternates between (l>>3) and (l>>3)+4 as i steps.
    float4* ob = reinterpret_cast<float4*>(out + (size_t)n * (size_t)HW
                                               + (size_t)gw * (32 * PIX));
    const int lh   = lane >> 3;
    const int rb0  = 8 * lh + ((lane & 7) ^ lh);            // i even base
    const int rb1  = 8 * (lh + 4) + ((lane & 7) ^ (lh + 4)); // i odd base
#pragma unroll
    for (int i = 0; i < 8; i += 2) {
        ob[32 * i + lane]        = tw[32 * i + rb0];
        ob[32 * (i + 1) + lane]  = tw[32 * i + rb1];
    }
}

// ---------------------------------------------------------------------------
// Fallback: per-pixel direct evaluation (odd shapes).
// ---------------------------------------------------------------------------
__global__ void __launch_bounds__(256) gmix_generic(
    const float* __restrict__ params,
    float* __restrict__ out,
    int H, int HW, float inv_wm1, float inv_hm1)
{
    const int n = blockIdx.y;
    const float* p = params + n * 28;
    float mux[NK], muy[NK], wkk[NK], s00[NK], s10[NK], s11[NK];
#pragma unroll
    for (int k = 0; k < NK; k++) {
        mux[k] = __ldg(p + k);        muy[k] = __ldg(p + 4 + k);
        wkk[k] = __ldg(p + 8 + k);
        s00[k] = __ldg(p + 12 + 4*k + 0);
        s10[k] = __ldg(p + 12 + 4*k + 2);
        s11[k] = __ldg(p + 12 + 4*k + 3);
    }
    const int c = blockIdx.x * blockDim.x + threadIdx.x;
    if (c >= HW) return;
    const int x_idx = c / H, y_idx = c - x_idx * H;
    const float px = (float)x_idx * inv_wm1, py = (float)y_idx * inv_hm1;
    float g = 0.0f, acc = 0.0f;
#pragma unroll
    for (int k = 0; k < NK; k++) {
        const float d0 = px - mux[k], d1 = py - muy[k];
        const float t0 = fmaf(s00[k], d0, s10[k] * d1);
        const float t1 = s11[k] * d1;
        const float e  = __expf(-0.5f * fmaf(t0, t0, t1 * t1));
        g += e;
        acc = fmaf(wkk[k], e, acc);
    }
    out[(size_t)n * (size_t)HW + c] =
        __saturatef(__fdividef(acc, fmaxf(GM_EPS, g)));
}

// ---------------------------------------------------------------------------
extern "C" void kernel_launch(void* const* d_in, const int* in_sizes, int n_in,
                              void* d_out, int out_size)
{
    int pi = 0;
    for (int i = 1; i < n_in; i++)
        if (in_sizes[i] > in_sizes[pi]) pi = i;
    const float* params = (const float*)d_in[pi];

    const int N  = in_sizes[pi] / 28;
    const int HW = out_size / N;
    int H = (int)(sqrt((double)HW) + 0.5);
    while (H > 1 && (HW % H) != 0) H--;
    const int W = HW / H;

    const float inv_wm1 = 1.0f / (float)(W - 1);
    const float inv_hm1 = 1.0f / (float)(H - 1);

    const int px_per_block = THR * PIX;   // 4096
    if ((H % PIX) == 0 && (HW % px_per_block) == 0) {
        dim3 grid(HW / px_per_block, N);
        gmix_fd<<<grid, THR>>>(params, (float*)d_out,
                               H, HW, inv_wm1, inv_hm1);
    } else {
        const int threads = 256;
        dim3 grid((HW + threads - 1) / threads, N);
        gmix_generic<<<grid, threads>>>(params, (float*)d_out,
                                        H, HW, inv_wm1, inv_hm1);
    }
}